// round 3
// baseline (speedup 1.0000x reference)
#include <cuda_runtime.h>
#include <cstdint>

#define NN 100000
#define NE 1600000
#define D  128

// ---------------- scratch: __device__ globals only (no allocations) ----------------
__device__ int   g_is64;
__device__ int   g_deg[NN];
__device__ int   g_off[NN];
__device__ int   g_cursor[NN];
__device__ int   g_srcs[NE];
__device__ float g_h[(size_t)NN * D];   // aggregated+normalized features (GEMM input)

// ---------------- dtype detection: int64 vs int32 edge buffer ----------------
// int64 little-endian with values < 2^31: every odd int32 word is 0.
// int32 layout: odd words are src indices, nonzero with overwhelming probability.
__global__ void detect_kernel(const int* __restrict__ ei32) {
    if (blockIdx.x == 0 && threadIdx.x == 0) {
        int nz = 0;
        #pragma unroll 8
        for (int i = 0; i < 512; i++) nz |= ei32[2 * i + 1];
        g_is64 = (nz == 0) ? 1 : 0;
    }
}

// ---------------- CSR build ----------------
__global__ void zero_deg_kernel(int n) {
    int i = blockIdx.x * blockDim.x + threadIdx.x;
    if (i < n) g_deg[i] = 0;
}

__device__ __forceinline__ int load_idx(const int* __restrict__ ei32,
                                        int is64, size_t pos) {
    // element at logical index pos; int64 stored little-endian -> low word at 2*pos
    return is64 ? ei32[2 * pos] : ei32[pos];
}

__global__ void count_kernel(const int* __restrict__ ei32, int E) {
    int e = blockIdx.x * blockDim.x + threadIdx.x;
    if (e < E) {
        int is64 = g_is64;
        int dst = load_idx(ei32, is64, (size_t)E + e);
        if ((unsigned)dst < (unsigned)NN)
            atomicAdd(&g_deg[dst], 1);
    }
}

// single-block exclusive scan of g_deg -> g_off (and g_cursor copy)
__global__ void scan_kernel(int n) {
    __shared__ int warp_sums[32];
    __shared__ int carry_s;
    int t = threadIdx.x, lane = t & 31, w = t >> 5;
    if (t == 0) carry_s = 0;
    __syncthreads();
    for (int base = 0; base < n; base += 1024) {
        int i = base + t;
        int v = (i < n) ? g_deg[i] : 0;
        int inc = v;
        #pragma unroll
        for (int d = 1; d < 32; d <<= 1) {
            int nb = __shfl_up_sync(0xffffffffu, inc, d);
            if (lane >= d) inc += nb;
        }
        if (lane == 31) warp_sums[w] = inc;
        __syncthreads();
        if (w == 0) {
            int s = warp_sums[lane];
            #pragma unroll
            for (int d = 1; d < 32; d <<= 1) {
                int nb = __shfl_up_sync(0xffffffffu, s, d);
                if (lane >= d) s += nb;
            }
            warp_sums[lane] = s;
        }
        __syncthreads();
        int warp_off = (w == 0) ? 0 : warp_sums[w - 1];
        int exc = carry_s + warp_off + inc - v;
        if (i < n) { g_off[i] = exc; g_cursor[i] = exc; }
        __syncthreads();
        if (t == 0) carry_s += warp_sums[31];
        __syncthreads();
    }
}

__global__ void fill_kernel(const int* __restrict__ ei32, int E) {
    int e = blockIdx.x * blockDim.x + threadIdx.x;
    if (e < E) {
        int is64 = g_is64;
        int src = load_idx(ei32, is64, (size_t)e);
        int dst = load_idx(ei32, is64, (size_t)E + e);
        if ((unsigned)dst < (unsigned)NN && (unsigned)src < (unsigned)NN) {
            int pos = atomicAdd(&g_cursor[dst], 1);
            if ((unsigned)pos < (unsigned)NE)
                g_srcs[pos] = src;
        }
    }
}

// ---------------- aggregation: warp per node, no float atomics ----------------
// reads X (external pointer), writes g_h (symbol)
__global__ void aggregate_kernel(const float* __restrict__ X, int n) {
    int node = blockIdx.x * (blockDim.x >> 5) + (threadIdx.x >> 5);
    int lane = threadIdx.x & 31;
    if (node >= n) return;
    int start = g_off[node];
    int cnt   = g_deg[node];
    const float4* X4 = (const float4*)X;

    float4 acc = make_float4(0.f, 0.f, 0.f, 0.f);
    int e = 0;
    for (; e + 4 <= cnt; e += 4) {
        int s0 = g_srcs[start + e + 0];
        int s1 = g_srcs[start + e + 1];
        int s2 = g_srcs[start + e + 2];
        int s3 = g_srcs[start + e + 3];
        float4 v0 = __ldg(X4 + (size_t)s0 * 32 + lane);
        float4 v1 = __ldg(X4 + (size_t)s1 * 32 + lane);
        float4 v2 = __ldg(X4 + (size_t)s2 * 32 + lane);
        float4 v3 = __ldg(X4 + (size_t)s3 * 32 + lane);
        acc.x += v0.x + v1.x + v2.x + v3.x;
        acc.y += v0.y + v1.y + v2.y + v3.y;
        acc.z += v0.z + v1.z + v2.z + v3.z;
        acc.w += v0.w + v1.w + v2.w + v3.w;
    }
    for (; e < cnt; e++) {
        int s = g_srcs[start + e];
        float4 v = __ldg(X4 + (size_t)s * 32 + lane);
        acc.x += v.x; acc.y += v.y; acc.z += v.z; acc.w += v.w;
    }
    float4 self = __ldg(X4 + (size_t)node * 32 + lane);
    float inv = 1.0f / (float)(cnt + 1);
    float4 h;
    h.x = (acc.x + self.x) * inv;
    h.y = (acc.y + self.y) * inv;
    h.z = (acc.z + self.z) * inv;
    h.w = (acc.w + self.w) * inv;
    ((float4*)g_h)[(size_t)node * 32 + lane] = h;
}

// ---------------- GEMM (M x 128) @ (128 x 128) + bias + leaky relu ----------------
// reads g_h (symbol), writes Out (external pointer)
// block: 256 threads, 128-row tile, 8x8 microtile per thread. Full K=128 in smem.
#define LDP 132   // padded row length (floats): 16B-aligned strides, no bank conflicts

__global__ __launch_bounds__(256)
void gemm_bias_lrelu_kernel(const float* __restrict__ W,
                            const float* __restrict__ bias,
                            float* __restrict__ Out, int M) {
    extern __shared__ float smem[];
    float* Ast = smem;              // [128][LDP]  A transposed: Ast[k][r]
    float* Ws  = smem + 128 * LDP;  // [128][LDP]  Ws[k][c]

    int block_row = blockIdx.x * 128;
    int rows = M - block_row; if (rows > 128) rows = 128;
    int t = threadIdx.x;

    const float* A = g_h;

    // load W (128x128) -> Ws[k][c]
    for (int i = t; i < 128 * 32; i += 256) {
        int k = i >> 5, c4 = i & 31;
        float4 v = ((const float4*)W)[i];
        *(float4*)(Ws + k * LDP + c4 * 4) = v;
    }
    // load A tile transposed -> Ast[k][r]
    for (int i = t; i < 128 * 32; i += 256) {
        int r = i >> 5, c4 = i & 31;
        float4 v = make_float4(0.f, 0.f, 0.f, 0.f);
        if (r < rows)
            v = ((const float4*)(A + (size_t)(block_row + r) * D))[c4];
        Ast[(c4 * 4 + 0) * LDP + r] = v.x;
        Ast[(c4 * 4 + 1) * LDP + r] = v.y;
        Ast[(c4 * 4 + 2) * LDP + r] = v.z;
        Ast[(c4 * 4 + 3) * LDP + r] = v.w;
    }
    __syncthreads();

    int tx = t & 15, ty = t >> 4;
    int c0 = tx * 8, r0 = ty * 8;

    float acc[8][8];
    #pragma unroll
    for (int i = 0; i < 8; i++)
        #pragma unroll
        for (int j = 0; j < 8; j++) acc[i][j] = 0.f;

    #pragma unroll 4
    for (int k = 0; k < 128; k++) {
        float4 a0 = *(const float4*)(Ast + k * LDP + r0);
        float4 a1 = *(const float4*)(Ast + k * LDP + r0 + 4);
        float4 w0 = *(const float4*)(Ws  + k * LDP + c0);
        float4 w1 = *(const float4*)(Ws  + k * LDP + c0 + 4);
        float a[8] = {a0.x, a0.y, a0.z, a0.w, a1.x, a1.y, a1.z, a1.w};
        float w[8] = {w0.x, w0.y, w0.z, w0.w, w1.x, w1.y, w1.z, w1.w};
        #pragma unroll
        for (int i = 0; i < 8; i++)
            #pragma unroll
            for (int j = 0; j < 8; j++)
                acc[i][j] += a[i] * w[j];
    }

    float bv[8];
    #pragma unroll
    for (int j = 0; j < 8; j++) bv[j] = bias[c0 + j];

    #pragma unroll
    for (int i = 0; i < 8; i++) {
        int r = r0 + i;
        if (r < rows) {
            float o[8];
            #pragma unroll
            for (int j = 0; j < 8; j++) {
                float v = acc[i][j] + bv[j];
                o[j] = (v >= 0.f) ? v : 0.01f * v;
            }
            float* dst = Out + (size_t)(block_row + r) * D + c0;
            *(float4*)(dst)     = make_float4(o[0], o[1], o[2], o[3]);
            *(float4*)(dst + 4) = make_float4(o[4], o[5], o[6], o[7]);
        }
    }
}

// ---------------- launch ----------------
extern "C" void kernel_launch(void* const* d_in, const int* in_sizes, int n_in,
                              void* d_out, int out_size) {
    const float* feat = (const float*)d_in[0];
    const int*   ei32 = (const int*)d_in[1];   // int32 OR int64 (auto-detected)
    const float* W1   = (const float*)d_in[2];
    const float* b1   = (const float*)d_in[3];
    const float* W2   = (const float*)d_in[4];
    const float* b2   = (const float*)d_in[5];
    float* out = (float*)d_out;

    int N = in_sizes[0] / D;      // 100000
    int E = in_sizes[1] / 2;      // 1600000

    const size_t gemm_smem = (size_t)2 * 128 * LDP * sizeof(float);
    cudaFuncSetAttribute(gemm_bias_lrelu_kernel,
                         cudaFuncAttributeMaxDynamicSharedMemorySize,
                         (int)gemm_smem);

    // dtype detection + CSR build (shared by both layers)
    detect_kernel<<<1, 32>>>(ei32);
    zero_deg_kernel<<<(N + 255) / 256, 256>>>(N);
    count_kernel<<<(E + 255) / 256, 256>>>(ei32, E);
    scan_kernel<<<1, 1024>>>(N);
    fill_kernel<<<(E + 255) / 256, 256>>>(ei32, E);

    int agg_blocks  = (N + 7) / 8;            // 8 warps per 256-thread block
    int gemm_blocks = (N + 127) / 128;

    // layer 1: aggregate(feat) -> g_h ; gemm(g_h, W1) -> d_out (layer-1 activations)
    aggregate_kernel<<<agg_blocks, 256>>>(feat, N);
    gemm_bias_lrelu_kernel<<<gemm_blocks, 256, gemm_smem>>>(W1, b1, out, N);
    // layer 2: aggregate(d_out) -> g_h ; gemm(g_h, W2) -> d_out (final)
    aggregate_kernel<<<agg_blocks, 256>>>(out, N);
    gemm_bias_lrelu_kernel<<<gemm_blocks, 256, gemm_smem>>>(W2, b2, out, N);
}

// round 5
// speedup vs baseline: 1.1407x; 1.1407x over previous
#include <cuda_runtime.h>
#include <cstdint>

#define NN 100000
#define NE 1600000
#define D  128
#define SCAN_CHUNK 2048
#define SCAN_NBLK ((NN + SCAN_CHUNK - 1) / SCAN_CHUNK)   // 49

// ---------------- scratch: __device__ globals only (no allocations) ----------------
__device__ int   g_is64;
__device__ int   g_deg[NN];
__device__ int   g_off[NN];
__device__ int   g_cursor[NN];
__device__ int   g_bsum[SCAN_NBLK];
__device__ int   g_srcs[NE];
__device__ float g_h[(size_t)NN * D];   // aggregated+normalized features (GEMM input)

// ---------------- dtype detection: int64 vs int32 edge buffer ----------------
__global__ void detect_kernel(const int* __restrict__ ei32) {
    if (blockIdx.x == 0 && threadIdx.x == 0) {
        int nz = 0;
        #pragma unroll 8
        for (int i = 0; i < 512; i++) nz |= ei32[2 * i + 1];
        g_is64 = (nz == 0) ? 1 : 0;
    }
}

// ---------------- CSR build ----------------
__global__ void zero_deg_kernel(int n) {
    int i = blockIdx.x * blockDim.x + threadIdx.x;
    if (i < n) g_deg[i] = 0;
}

__device__ __forceinline__ int load_idx(const int* __restrict__ ei32,
                                        int is64, size_t pos) {
    return is64 ? ei32[2 * pos] : ei32[pos];
}

__global__ void count_kernel(const int* __restrict__ ei32, int E) {
    int e = blockIdx.x * blockDim.x + threadIdx.x;
    if (e < E) {
        int is64 = g_is64;
        int dst = load_idx(ei32, is64, (size_t)E + e);
        if ((unsigned)dst < (unsigned)NN)
            atomicAdd(&g_deg[dst], 1);
    }
}

// ------- hierarchical scan: local scan -> block-sum scan -> add offsets -------
__global__ __launch_bounds__(1024)
void scan_local_kernel(int n) {
    __shared__ int wsum[32];
    int t = threadIdx.x, lane = t & 31, w = t >> 5;
    int base = blockIdx.x * SCAN_CHUNK;
    int i0 = base + 2 * t, i1 = i0 + 1;
    int v0 = (i0 < n) ? g_deg[i0] : 0;
    int v1 = (i1 < n) ? g_deg[i1] : 0;
    int s = v0 + v1;
    int inc = s;
    #pragma unroll
    for (int d = 1; d < 32; d <<= 1) {
        int nb = __shfl_up_sync(0xffffffffu, inc, d);
        if (lane >= d) inc += nb;
    }
    if (lane == 31) wsum[w] = inc;
    __syncthreads();
    if (w == 0) {
        int x = wsum[lane];
        #pragma unroll
        for (int d = 1; d < 32; d <<= 1) {
            int nb = __shfl_up_sync(0xffffffffu, x, d);
            if (lane >= d) x += nb;
        }
        wsum[lane] = x;
    }
    __syncthreads();
    int woff = (w == 0) ? 0 : wsum[w - 1];
    int exc = woff + inc - s;                 // exclusive prefix within block
    if (i0 < n) g_off[i0] = exc;
    if (i1 < n) g_off[i1] = exc + v0;
    if (t == 1023) g_bsum[blockIdx.x] = wsum[31];   // block total (single writer!)
}

__global__ void scan_bsum_kernel(int nb) {
    int lane = threadIdx.x;                   // 32 threads
    int v0 = (lane < nb) ? g_bsum[lane] : 0;
    int v1 = (lane + 32 < nb) ? g_bsum[lane + 32] : 0;
    int s0 = v0;
    #pragma unroll
    for (int d = 1; d < 32; d <<= 1) {
        int nb_ = __shfl_up_sync(0xffffffffu, s0, d);
        if (lane >= d) s0 += nb_;
    }
    int tot0 = __shfl_sync(0xffffffffu, s0, 31);
    int s1 = v1;
    #pragma unroll
    for (int d = 1; d < 32; d <<= 1) {
        int nb_ = __shfl_up_sync(0xffffffffu, s1, d);
        if (lane >= d) s1 += nb_;
    }
    s1 += tot0;
    if (lane < nb)      g_bsum[lane]      = s0 - v0;   // exclusive
    if (lane + 32 < nb) g_bsum[lane + 32] = s1 - v1;
}

__global__ __launch_bounds__(1024)
void scan_add_kernel(int n) {
    int add = g_bsum[blockIdx.x];
    int base = blockIdx.x * SCAN_CHUNK;
    int i0 = base + 2 * threadIdx.x, i1 = i0 + 1;
    if (i0 < n) { int o = g_off[i0] + add; g_off[i0] = o; g_cursor[i0] = o; }
    if (i1 < n) { int o = g_off[i1] + add; g_off[i1] = o; g_cursor[i1] = o; }
}

__global__ void fill_kernel(const int* __restrict__ ei32, int E) {
    int e = blockIdx.x * blockDim.x + threadIdx.x;
    if (e < E) {
        int is64 = g_is64;
        int src = load_idx(ei32, is64, (size_t)e);
        int dst = load_idx(ei32, is64, (size_t)E + e);
        if ((unsigned)dst < (unsigned)NN && (unsigned)src < (unsigned)NN) {
            int pos = atomicAdd(&g_cursor[dst], 1);
            if ((unsigned)pos < (unsigned)NE)
                g_srcs[pos] = src;
        }
    }
}

// ---------------- aggregation: warp per node, no float atomics ----------------
__global__ void aggregate_kernel(const float* __restrict__ X, int n) {
    int node = blockIdx.x * (blockDim.x >> 5) + (threadIdx.x >> 5);
    int lane = threadIdx.x & 31;
    if (node >= n) return;
    int start = g_off[node];
    int cnt   = g_deg[node];
    const float4* X4 = (const float4*)X;

    float4 acc = make_float4(0.f, 0.f, 0.f, 0.f);
    int e = 0;
    for (; e + 4 <= cnt; e += 4) {
        int s0 = g_srcs[start + e + 0];
        int s1 = g_srcs[start + e + 1];
        int s2 = g_srcs[start + e + 2];
        int s3 = g_srcs[start + e + 3];
        float4 v0 = __ldg(X4 + (size_t)s0 * 32 + lane);
        float4 v1 = __ldg(X4 + (size_t)s1 * 32 + lane);
        float4 v2 = __ldg(X4 + (size_t)s2 * 32 + lane);
        float4 v3 = __ldg(X4 + (size_t)s3 * 32 + lane);
        acc.x += v0.x + v1.x + v2.x + v3.x;
        acc.y += v0.y + v1.y + v2.y + v3.y;
        acc.z += v0.z + v1.z + v2.z + v3.z;
        acc.w += v0.w + v1.w + v2.w + v3.w;
    }
    for (; e < cnt; e++) {
        int s = g_srcs[start + e];
        float4 v = __ldg(X4 + (size_t)s * 32 + lane);
        acc.x += v.x; acc.y += v.y; acc.z += v.z; acc.w += v.w;
    }
    float4 self = __ldg(X4 + (size_t)node * 32 + lane);
    float inv = 1.0f / (float)(cnt + 1);
    float4 h;
    h.x = (acc.x + self.x) * inv;
    h.y = (acc.y + self.y) * inv;
    h.z = (acc.z + self.z) * inv;
    h.w = (acc.w + self.w) * inv;
    ((float4*)g_h)[(size_t)node * 32 + lane] = h;
}

// ---------------- GEMM (M x 128) @ (128 x 128) + bias + leaky relu ----------------
#define LDP 132

__global__ __launch_bounds__(256)
void gemm_bias_lrelu_kernel(const float* __restrict__ W,
                            const float* __restrict__ bias,
                            float* __restrict__ Out, int M) {
    extern __shared__ float smem[];
    float* Ast = smem;              // [128][LDP]  A transposed: Ast[k][r]
    float* Ws  = smem + 128 * LDP;  // [128][LDP]  Ws[k][c]

    int block_row = blockIdx.x * 128;
    int rows = M - block_row; if (rows > 128) rows = 128;
    int t = threadIdx.x;

    const float* A = g_h;

    for (int i = t; i < 128 * 32; i += 256) {
        int k = i >> 5, c4 = i & 31;
        float4 v = ((const float4*)W)[i];
        *(float4*)(Ws + k * LDP + c4 * 4) = v;
    }
    for (int i = t; i < 128 * 32; i += 256) {
        int r = i >> 5, c4 = i & 31;
        float4 v = make_float4(0.f, 0.f, 0.f, 0.f);
        if (r < rows)
            v = ((const float4*)(A + (size_t)(block_row + r) * D))[c4];
        Ast[(c4 * 4 + 0) * LDP + r] = v.x;
        Ast[(c4 * 4 + 1) * LDP + r] = v.y;
        Ast[(c4 * 4 + 2) * LDP + r] = v.z;
        Ast[(c4 * 4 + 3) * LDP + r] = v.w;
    }
    __syncthreads();

    int tx = t & 15, ty = t >> 4;
    int c0 = tx * 8, r0 = ty * 8;

    float acc[8][8];
    #pragma unroll
    for (int i = 0; i < 8; i++)
        #pragma unroll
        for (int j = 0; j < 8; j++) acc[i][j] = 0.f;

    #pragma unroll 4
    for (int k = 0; k < 128; k++) {
        float4 a0 = *(const float4*)(Ast + k * LDP + r0);
        float4 a1 = *(const float4*)(Ast + k * LDP + r0 + 4);
        float4 w0 = *(const float4*)(Ws  + k * LDP + c0);
        float4 w1 = *(const float4*)(Ws  + k * LDP + c0 + 4);
        float a[8] = {a0.x, a0.y, a0.z, a0.w, a1.x, a1.y, a1.z, a1.w};
        float w[8] = {w0.x, w0.y, w0.z, w0.w, w1.x, w1.y, w1.z, w1.w};
        #pragma unroll
        for (int i = 0; i < 8; i++)
            #pragma unroll
            for (int j = 0; j < 8; j++)
                acc[i][j] += a[i] * w[j];
    }

    float bv[8];
    #pragma unroll
    for (int j = 0; j < 8; j++) bv[j] = bias[c0 + j];

    #pragma unroll
    for (int i = 0; i < 8; i++) {
        int r = r0 + i;
        if (r < rows) {
            float o[8];
            #pragma unroll
            for (int j = 0; j < 8; j++) {
                float v = acc[i][j] + bv[j];
                o[j] = (v >= 0.f) ? v : 0.01f * v;
            }
            float* dst = Out + (size_t)(block_row + r) * D + c0;
            *(float4*)(dst)     = make_float4(o[0], o[1], o[2], o[3]);
            *(float4*)(dst + 4) = make_float4(o[4], o[5], o[6], o[7]);
        }
    }
}

// ---------------- launch ----------------
extern "C" void kernel_launch(void* const* d_in, const int* in_sizes, int n_in,
                              void* d_out, int out_size) {
    const float* feat = (const float*)d_in[0];
    const int*   ei32 = (const int*)d_in[1];   // int32 OR int64 (auto-detected)
    const float* W1   = (const float*)d_in[2];
    const float* b1   = (const float*)d_in[3];
    const float* W2   = (const float*)d_in[4];
    const float* b2   = (const float*)d_in[5];
    float* out = (float*)d_out;

    int N = in_sizes[0] / D;      // 100000
    int E = in_sizes[1] / 2;      // 1600000

    const size_t gemm_smem = (size_t)2 * 128 * LDP * sizeof(float);
    cudaFuncSetAttribute(gemm_bias_lrelu_kernel,
                         cudaFuncAttributeMaxDynamicSharedMemorySize,
                         (int)gemm_smem);

    // dtype detection + CSR build (shared by both layers)
    detect_kernel<<<1, 32>>>(ei32);
    zero_deg_kernel<<<(N + 255) / 256, 256>>>(N);
    count_kernel<<<(E + 255) / 256, 256>>>(ei32, E);
    scan_local_kernel<<<SCAN_NBLK, 1024>>>(N);
    scan_bsum_kernel<<<1, 32>>>(SCAN_NBLK);
    scan_add_kernel<<<SCAN_NBLK, 1024>>>(N);
    fill_kernel<<<(E + 255) / 256, 256>>>(ei32, E);

    int agg_blocks  = (N + 7) / 8;            // 8 warps per 256-thread block
    int gemm_blocks = (N + 127) / 128;

    // layer 1
    aggregate_kernel<<<agg_blocks, 256>>>(feat, N);
    gemm_bias_lrelu_kernel<<<gemm_blocks, 256, gemm_smem>>>(W1, b1, out, N);
    // layer 2
    aggregate_kernel<<<agg_blocks, 256>>>(out, N);
    gemm_bias_lrelu_kernel<<<gemm_blocks, 256, gemm_smem>>>(W2, b2, out, N);
}